// round 10
// baseline (speedup 1.0000x reference)
#include <cuda_runtime.h>
#include <stdint.h>
#include <math.h>
#include <mma.h>

using namespace nvcuda;

#define HW     128
#define BATCH  2
#define CH     128
#define NPIX   (HW*HW)            // 16384
#define ITERS  10

#define NT_LC   16384             // 4 images x 4096 tiles
#define NT_CF   8192              // 2 images
#define CFPAD   272               // cf1 cin pad (multiple of 16)
#define VPL_LC  (128*NT_LC)
#define VPL_CF  (CFPAD*NT_CF)
#define MPL_LC  (128*NT_LC)
#define MPL_CF  (128*NT_CF)

// ---------------- scratch (static device allocations; no cudaMalloc) ----------------
__device__ float g_lf0 [BATCH*CH*NPIX];
__device__ float g_lf1 [BATCH*CH*NPIX];
__device__ float g_tmp [BATCH*CH*NPIX];
__device__ float g_tmp2[BATCH*CH*NPIX];
__device__ float g_x   [BATCH*NPIX*CH];
__device__ float g_y   [BATCH*NPIX*CH];
__device__ float g_flow[BATCH*2*NPIX];
__device__ float g_fi  [BATCH*2*NPIX];
__device__ float g_hcat[BATCH*258*NPIX];
__device__ float g_h2  [BATCH*64*NPIX];
__device__ float g_M   [CH*CH];
__device__ float g_u   [CH];
__device__ float g_bv  [CH];
__device__ float g_c   [1];
__device__ float g_bscal[BATCH*NPIX];
// Winograd buffers
__device__ float g_V   [16 * VPL_CF];        // 16*VPL_CF > 16*VPL_LC? VPL_LC=2.09M, VPL_CF=2.23M ok
__device__ float g_Mw  [16 * MPL_LC];
__device__ float g_U1h [16 * 128 * 128];
__device__ float g_U1l [16 * 128 * 128];
__device__ float g_U2h [16 * 128 * 128];
__device__ float g_U2l [16 * 128 * 128];
__device__ float g_Uch [16 * CFPAD * 128];
__device__ float g_Ucl [16 * CFPAD * 128];

// ---------------- helpers ----------------
__device__ __forceinline__ float gelu_f(float v) {
    return 0.5f * v * (1.0f + erff(v * 0.70710678118654752f));
}
__device__ __forceinline__ float sigmoid_f(float v) {
    return 1.0f / (1.0f + expf(-v));
}

#define ACT_NONE 0
#define ACT_GELU 1
#define ACT_SIGM 2

// ---------------- prep: M = Wq^T Wk ; u = Wq^T kb ; bv = Wk^T qb ; c = qb.kb ----------------
__global__ void prepM_kernel(const float* __restrict__ qw, const float* __restrict__ kw,
                             float* __restrict__ M)
{
    int i = blockIdx.x, j = threadIdx.x;
    float s = 0.f;
    for (int d = 0; d < CH; d++)
        s += qw[d * CH + i] * kw[d * CH + j];
    M[i * CH + j] = s;
}

__global__ void prepUV_kernel(const float* __restrict__ qw, const float* __restrict__ kw,
                              const float* __restrict__ qb, const float* __restrict__ kb,
                              float* __restrict__ u, float* __restrict__ bv, float* __restrict__ c)
{
    int j = threadIdx.x;
    float su = 0.f, sb = 0.f;
    for (int d = 0; d < CH; d++) {
        su += qw[d * CH + j] * kb[d];
        sb += kw[d * CH + j] * qb[d];
    }
    u[j] = su;
    bv[j] = sb;
    if (j == 0) {
        float cc = 0.f;
        for (int d = 0; d < CH; d++) cc += qb[d] * kb[d];
        c[0] = cc;
    }
}

// ---------------- Winograd F(2x2,3x3) ----------------
// weight transform -> tf32 hi/lo pair: U{h,l}[t][cin][cout]
__global__ void wino_wt_kernel(const float* __restrict__ w,
                               float* __restrict__ Uh, float* __restrict__ Ul,
                               int Cin, int CinPad, int Cout)
{
    int i = blockIdx.x * 256 + threadIdx.x;
    if (i >= CinPad * Cout) return;
    int ci = i / Cout, co = i % Cout;
    float g[3][3];
    #pragma unroll
    for (int r = 0; r < 3; r++)
        #pragma unroll
        for (int cc = 0; cc < 3; cc++)
            g[r][cc] = (ci < Cin) ? w[((size_t)co * Cin + ci) * 9 + r * 3 + cc] : 0.f;
    float t[4][3];
    #pragma unroll
    for (int cc = 0; cc < 3; cc++) {
        t[0][cc] = g[0][cc];
        t[1][cc] = 0.5f * (g[0][cc] + g[1][cc] + g[2][cc]);
        t[2][cc] = 0.5f * (g[0][cc] - g[1][cc] + g[2][cc]);
        t[3][cc] = g[2][cc];
    }
    #pragma unroll
    for (int r = 0; r < 4; r++) {
        float u0 = t[r][0];
        float u1 = 0.5f * (t[r][0] + t[r][1] + t[r][2]);
        float u2 = 0.5f * (t[r][0] - t[r][1] + t[r][2]);
        float u3 = t[r][2];
        float uv[4] = {u0, u1, u2, u3};
        #pragma unroll
        for (int cc = 0; cc < 4; cc++) {
            size_t o = (size_t)(r * 4 + cc) * CinPad * Cout + (size_t)ci * Cout + co;
            float h = wmma::__float_to_tf32(uv[cc]);
            Uh[o] = h;
            Ul[o] = wmma::__float_to_tf32(uv[cc] - h);
        }
    }
}

// input transform: V[t][ci][tile]
__global__ __launch_bounds__(256) void wino_in_kernel(
    const float* __restrict__ srcA, const float* __restrict__ srcB,
    float* __restrict__ V, int Cin, int CinPad, int NT, int vplane)
{
    const int tg = blockIdx.x * 32 + (threadIdx.x & 31);
    const int ci = blockIdx.y * 8 + (threadIdx.x >> 5);
    const int img = tg >> 12;
    const int within = tg & 4095;
    const int ty = within >> 6, tx = within & 63;
    const float* src = (img < 2) ? srcA : srcB;
    const int b = img & 1;

    float d[4][4];
    if (ci < Cin) {
        const float* p = src + (size_t)(b * Cin + ci) * NPIX;
        const int yb = 2 * ty - 1, xb = 2 * tx - 1;
        #pragma unroll
        for (int r = 0; r < 4; r++) {
            int yy = yb + r;
            #pragma unroll
            for (int cc = 0; cc < 4; cc++) {
                int xx = xb + cc;
                d[r][cc] = ((unsigned)yy < (unsigned)HW && (unsigned)xx < (unsigned)HW)
                         ? p[yy * HW + xx] : 0.f;
            }
        }
    } else {
        #pragma unroll
        for (int r = 0; r < 4; r++)
            #pragma unroll
            for (int cc = 0; cc < 4; cc++) d[r][cc] = 0.f;
    }

    float tm[4][4];
    #pragma unroll
    for (int j = 0; j < 4; j++) {
        tm[0][j] = d[0][j] - d[2][j];
        tm[1][j] = d[1][j] + d[2][j];
        tm[2][j] = d[2][j] - d[1][j];
        tm[3][j] = d[1][j] - d[3][j];
    }
    float v4[4][4];
    #pragma unroll
    for (int i = 0; i < 4; i++) {
        v4[i][0] = tm[i][0] - tm[i][2];
        v4[i][1] = tm[i][1] + tm[i][2];
        v4[i][2] = tm[i][2] - tm[i][1];
        v4[i][3] = tm[i][1] - tm[i][3];
    }
    #pragma unroll
    for (int r = 0; r < 4; r++)
        #pragma unroll
        for (int cc = 0; cc < 4; cc++)
            V[(size_t)(r * 4 + cc) * vplane + (size_t)ci * NT + tg] = v4[r][cc];
}

// per-t tensor-core GEMM (tf32x3): Mw[t][co][tile] = sum_ci U[t][ci][co] * V[t][ci][tile]
// block tile 128(co) x 128(tile); 8 warps = 2(m) x 4(n); K staged in chunks of 16.
#define WG_LD 136
__global__ __launch_bounds__(256) void wino_gemm_tc_kernel(
    const float* __restrict__ Uh, const float* __restrict__ Ul,
    const float* __restrict__ V, float* __restrict__ Mw,
    int CinPad, int NT, int uplane, int vplane, int mplane)
{
    __shared__ float Ahi[16 * WG_LD];
    __shared__ float Alo[16 * WG_LD];
    __shared__ float Bhi[16 * WG_LD];
    __shared__ float Blo[16 * WG_LD];

    const int tid = threadIdx.x;
    const int warp = tid >> 5;
    const int wm = warp & 1;          // m offset 64*wm
    const int wn = warp >> 1;         // n offset 32*wn
    const int t16 = blockIdx.y;
    const int n0 = blockIdx.x * 128;
    const float* Uht = Uh + (size_t)t16 * uplane;
    const float* Ult = Ul + (size_t)t16 * uplane;
    const float* Vt  = V + (size_t)t16 * vplane;
    float* Mt = Mw + (size_t)t16 * mplane;

    wmma::fragment<wmma::accumulator, 16, 16, 8, float> acc[4][2];
    #pragma unroll
    for (int i = 0; i < 4; i++)
        #pragma unroll
        for (int j = 0; j < 2; j++)
            wmma::fill_fragment(acc[i][j], 0.f);

    const int nchunks = CinPad >> 4;
    for (int ch = 0; ch < nchunks; ch++) {
        const int k0 = ch * 16;
        // stage A chunk: [16][128] of Uh/Ul (already tf32-split) -> smem stride WG_LD
        for (int idx = tid; idx < 512; idx += 256) {
            int kk = idx >> 5, c4 = (idx & 31) * 4;
            *(float4*)&Ahi[kk * WG_LD + c4] = *(const float4*)&Uht[(size_t)(k0 + kk) * 128 + c4];
            *(float4*)&Alo[kk * WG_LD + c4] = *(const float4*)&Ult[(size_t)(k0 + kk) * 128 + c4];
        }
        // stage B chunk: V [16][128] fp32 -> hi/lo split
        for (int idx = tid; idx < 512; idx += 256) {
            int kk = idx >> 5, c4 = (idx & 31) * 4;
            float4 v = *(const float4*)&Vt[(size_t)(k0 + kk) * NT + n0 + c4];
            float h0 = wmma::__float_to_tf32(v.x);
            float h1 = wmma::__float_to_tf32(v.y);
            float h2 = wmma::__float_to_tf32(v.z);
            float h3 = wmma::__float_to_tf32(v.w);
            int o = kk * WG_LD + c4;
            Bhi[o+0] = h0; Bhi[o+1] = h1; Bhi[o+2] = h2; Bhi[o+3] = h3;
            Blo[o+0] = wmma::__float_to_tf32(v.x - h0);
            Blo[o+1] = wmma::__float_to_tf32(v.y - h1);
            Blo[o+2] = wmma::__float_to_tf32(v.z - h2);
            Blo[o+3] = wmma::__float_to_tf32(v.w - h3);
        }
        __syncthreads();

        #pragma unroll
        for (int ks = 0; ks < 2; ks++) {
            const int kb = ks * 8;
            wmma::fragment<wmma::matrix_a, 16, 16, 8, wmma::precision::tf32, wmma::col_major> ah[4], al[4];
            wmma::fragment<wmma::matrix_b, 16, 16, 8, wmma::precision::tf32, wmma::row_major> bh[2], bl[2];
            #pragma unroll
            for (int i = 0; i < 4; i++) {
                int m = 64 * wm + 16 * i;
                wmma::load_matrix_sync(ah[i], &Ahi[kb * WG_LD + m], WG_LD);
                wmma::load_matrix_sync(al[i], &Alo[kb * WG_LD + m], WG_LD);
            }
            #pragma unroll
            for (int j = 0; j < 2; j++) {
                int n = 32 * wn + 16 * j;
                wmma::load_matrix_sync(bh[j], &Bhi[kb * WG_LD + n], WG_LD);
                wmma::load_matrix_sync(bl[j], &Blo[kb * WG_LD + n], WG_LD);
            }
            #pragma unroll
            for (int i = 0; i < 4; i++)
                #pragma unroll
                for (int j = 0; j < 2; j++) {
                    wmma::mma_sync(acc[i][j], ah[i], bl[j], acc[i][j]);
                    wmma::mma_sync(acc[i][j], al[i], bh[j], acc[i][j]);
                    wmma::mma_sync(acc[i][j], ah[i], bh[j], acc[i][j]);
                }
        }
        __syncthreads();
    }

    #pragma unroll
    for (int i = 0; i < 4; i++)
        #pragma unroll
        for (int j = 0; j < 2; j++) {
            int m = 64 * wm + 16 * i;
            int n = 32 * wn + 16 * j;
            wmma::store_matrix_sync(Mt + (size_t)m * NT + n0 + n, acc[i][j], NT, wmma::mem_row_major);
        }
}

// inverse transform + bias + act -> NCHW dst
__global__ __launch_bounds__(256) void wino_out_kernel(
    const float* __restrict__ Mw, const float* __restrict__ bias,
    float* __restrict__ dstA, float* __restrict__ dstB,
    int Cout, int NT, int mplane, int act)
{
    const int tg = blockIdx.x * 32 + (threadIdx.x & 31);
    const int co = blockIdx.y * 8 + (threadIdx.x >> 5);
    const int img = tg >> 12;
    const int within = tg & 4095;
    const int ty = within >> 6, tx = within & 63;
    float* dst = (img < 2) ? dstA : dstB;
    const int b = img & 1;

    float m[4][4];
    #pragma unroll
    for (int r = 0; r < 4; r++)
        #pragma unroll
        for (int cc = 0; cc < 4; cc++)
            m[r][cc] = Mw[(size_t)(r * 4 + cc) * mplane + (size_t)co * NT + tg];

    float s[2][4];
    #pragma unroll
    for (int j = 0; j < 4; j++) {
        s[0][j] = m[0][j] + m[1][j] + m[2][j];
        s[1][j] = m[1][j] - m[2][j] - m[3][j];
    }
    float bvv = bias[co];
    float y00 = s[0][0] + s[0][1] + s[0][2] + bvv;
    float y01 = s[0][1] - s[0][2] - s[0][3] + bvv;
    float y10 = s[1][0] + s[1][1] + s[1][2] + bvv;
    float y11 = s[1][1] - s[1][2] - s[1][3] + bvv;
    if (act == ACT_GELU) {
        y00 = gelu_f(y00); y01 = gelu_f(y01); y10 = gelu_f(y10); y11 = gelu_f(y11);
    }
    float* q = dst + (size_t)(b * Cout + co) * NPIX + (2 * ty) * HW + 2 * tx;
    q[0] = y00; q[1] = y01; q[HW] = y10; q[HW + 1] = y11;
}

// ---------------- direct NCHW 3x3 conv (cf2 / cf3) ----------------
template<int COT>
__global__ __launch_bounds__(256, 2) void conv3x3_kernel(
    const float* __restrict__ in, const float* __restrict__ wgt,
    const float* __restrict__ bias, float* __restrict__ out,
    int Cin, int Cout, int act)
{
    __shared__ float s_in[8][34][34];
    __shared__ __align__(16) float s_w[8][COT][12];

    const int tid = threadIdx.x;
    const int tx = tid & 15, ty = tid >> 4;
    const int x0 = blockIdx.x * 32, y0 = blockIdx.y * 32;
    const int nco = (Cout + COT - 1) / COT;
    const int bb  = blockIdx.z / nco;
    const int co0 = (blockIdx.z % nco) * COT;

    float acc[COT][2][2];
    #pragma unroll
    for (int c = 0; c < COT; c++)
        #pragma unroll
        for (int i = 0; i < 2; i++)
            #pragma unroll
            for (int j = 0; j < 2; j++) acc[c][i][j] = 0.f;

    for (int c0 = 0; c0 < Cin; c0 += 8) {
        for (int idx = tid; idx < 8 * 1156; idx += 256) {
            int ci = idx / 1156;
            int r  = (idx % 1156) / 34;
            int cc = idx % 34;
            int gy = y0 - 1 + r, gx = x0 - 1 + cc;
            int cin = c0 + ci;
            float v = 0.f;
            if (cin < Cin && (unsigned)gy < (unsigned)HW && (unsigned)gx < (unsigned)HW)
                v = in[((size_t)(bb * Cin + cin) * HW + gy) * HW + gx];
            s_in[ci][r][cc] = v;
        }
        for (int idx = tid; idx < 8 * COT * 9; idx += 256) {
            int ci = idx / (COT * 9);
            int co = (idx % (COT * 9)) / 9;
            int k  = idx % 9;
            int cin = c0 + ci, cog = co0 + co;
            float v = 0.f;
            if (cin < Cin && cog < Cout)
                v = wgt[((size_t)cog * Cin + cin) * 9 + k];
            s_w[ci][co][k] = v;
        }
        __syncthreads();

        #pragma unroll
        for (int ci = 0; ci < 8; ci++) {
            float v[4][4];
            #pragma unroll
            for (int i = 0; i < 4; i++) {
                float2 a = *(const float2*)&s_in[ci][ty * 2 + i][tx * 2];
                float2 b = *(const float2*)&s_in[ci][ty * 2 + i][tx * 2 + 2];
                v[i][0] = a.x; v[i][1] = a.y; v[i][2] = b.x; v[i][3] = b.y;
            }
            #pragma unroll
            for (int co = 0; co < COT; co++) {
                float4 wa = *(const float4*)&s_w[ci][co][0];
                float4 wb = *(const float4*)&s_w[ci][co][4];
                float w8  = s_w[ci][co][8];
                #pragma unroll
                for (int i2 = 0; i2 < 2; i2++)
                    #pragma unroll
                    for (int j2 = 0; j2 < 2; j2++) {
                        float a = acc[co][i2][j2];
                        a += v[i2+0][j2+0] * wa.x;
                        a += v[i2+0][j2+1] * wa.y;
                        a += v[i2+0][j2+2] * wa.z;
                        a += v[i2+1][j2+0] * wa.w;
                        a += v[i2+1][j2+1] * wb.x;
                        a += v[i2+1][j2+2] * wb.y;
                        a += v[i2+2][j2+0] * wb.z;
                        a += v[i2+2][j2+1] * wb.w;
                        a += v[i2+2][j2+2] * w8;
                        acc[co][i2][j2] = a;
                    }
            }
        }
        __syncthreads();
    }

    #pragma unroll
    for (int co = 0; co < COT; co++) {
        int cog = co0 + co;
        if (cog >= Cout) break;
        float bvv = bias[cog];
        #pragma unroll
        for (int i2 = 0; i2 < 2; i2++)
            #pragma unroll
            for (int j2 = 0; j2 < 2; j2++) {
                int oy = y0 + ty * 2 + i2, ox = x0 + tx * 2 + j2;
                float v = acc[co][i2][j2] + bvv;
                if (act == ACT_GELU) v = gelu_f(v);
                else if (act == ACT_SIGM) v = sigmoid_f(v);
                out[((size_t)(bb * Cout + cog) * HW + oy) * HW + ox] = v;
            }
    }
}

// ---------------- fused flow-refiner chain ----------------
#define FR_OFF_W1 0
#define FR_OFF_B1 288
#define FR_OFF_W2 304
#define FR_OFF_B2 2608
#define FR_OFF_W3 2624
#define FR_OFF_B3 2912
#define FR_OFF_FI 2916
#define FR_OFF_T1 3884
#define FR_OFF_T2 10284
#define FR_SMEM_FLOATS 15468
#define FR_SMEM_BYTES (FR_SMEM_FLOATS * 4)

__global__ __launch_bounds__(256) void fr_fused_kernel(
    const float* __restrict__ fi,
    const float* __restrict__ w1, const float* __restrict__ b1,
    const float* __restrict__ w2, const float* __restrict__ b2,
    const float* __restrict__ w3, const float* __restrict__ b3,
    float* __restrict__ flow)
{
    extern __shared__ float sm[];
    const int tid = threadIdx.x;
    const int x0 = blockIdx.x * 16, y0 = blockIdx.y * 16;
    const int b = blockIdx.z;

    for (int u = tid; u < 288;  u += 256) sm[FR_OFF_W1 + u] = w1[u];
    for (int u = tid; u < 16;   u += 256) sm[FR_OFF_B1 + u] = b1[u];
    for (int u = tid; u < 2304; u += 256) sm[FR_OFF_W2 + u] = w2[u];
    for (int u = tid; u < 16;   u += 256) sm[FR_OFF_B2 + u] = b2[u];
    for (int u = tid; u < 288;  u += 256) sm[FR_OFF_W3 + u] = w3[u];
    for (int u = tid; u < 2;    u += 256) sm[FR_OFF_B3 + u] = b3[u];
    for (int u = tid; u < 2 * 484; u += 256) {
        int ci = u / 484;
        int rem = u % 484;
        int r = rem / 22, c = rem % 22;
        int gy = y0 - 3 + r, gx = x0 - 3 + c;
        float v = 0.f;
        if ((unsigned)gy < (unsigned)HW && (unsigned)gx < (unsigned)HW)
            v = fi[(size_t)(b * 2 + ci) * NPIX + gy * HW + gx];
        sm[FR_OFF_FI + u] = v;
    }
    __syncthreads();

    for (int u = tid; u < 16 * 400; u += 256) {
        int co = u / 400;
        int rem = u % 400;
        int r = rem / 20, c = rem % 20;
        int gy = y0 - 2 + r, gx = x0 - 2 + c;
        float v = 0.f;
        if ((unsigned)gy < (unsigned)HW && (unsigned)gx < (unsigned)HW) {
            float s = sm[FR_OFF_B1 + co];
            #pragma unroll
            for (int ci = 0; ci < 2; ci++)
                #pragma unroll
                for (int dy = 0; dy < 3; dy++)
                    #pragma unroll
                    for (int dx = 0; dx < 3; dx++)
                        s += sm[FR_OFF_FI + (ci * 22 + r + dy) * 22 + c + dx]
                           * sm[FR_OFF_W1 + (co * 2 + ci) * 9 + dy * 3 + dx];
            v = gelu_f(s);
        }
        sm[FR_OFF_T1 + u] = v;
    }
    __syncthreads();

    for (int u = tid; u < 16 * 324; u += 256) {
        int co = u / 324;
        int rem = u % 324;
        int r = rem / 18, c = rem % 18;
        int gy = y0 - 1 + r, gx = x0 - 1 + c;
        float v = 0.f;
        if ((unsigned)gy < (unsigned)HW && (unsigned)gx < (unsigned)HW) {
            float s = sm[FR_OFF_B2 + co];
            #pragma unroll
            for (int ci = 0; ci < 16; ci++) {
                const float* t1p = &sm[FR_OFF_T1 + (ci * 20 + r) * 20 + c];
                const float* wp  = &sm[FR_OFF_W2 + (co * 16 + ci) * 9];
                s += t1p[0]  * wp[0] + t1p[1]  * wp[1] + t1p[2]  * wp[2];
                s += t1p[20] * wp[3] + t1p[21] * wp[4] + t1p[22] * wp[5];
                s += t1p[40] * wp[6] + t1p[41] * wp[7] + t1p[42] * wp[8];
            }
            v = gelu_f(s);
        }
        sm[FR_OFF_T2 + u] = v;
    }
    __syncthreads();

    for (int u = tid; u < 2 * 256; u += 256) {
        int f = u / 256;
        int rem = u % 256;
        int r = rem / 16, c = rem % 16;
        float s = sm[FR_OFF_B3 + f];
        #pragma unroll
        for (int ci = 0; ci < 16; ci++) {
            const float* t2p = &sm[FR_OFF_T2 + (ci * 18 + r) * 18 + c];
            const float* wp  = &sm[FR_OFF_W3 + (f * 16 + ci) * 9];
            s += t2p[0]  * wp[0] + t2p[1]  * wp[1] + t2p[2]  * wp[2];
            s += t2p[18] * wp[3] + t2p[19] * wp[4] + t2p[20] * wp[5];
            s += t2p[36] * wp[6] + t2p[37] * wp[7] + t2p[38] * wp[8];
        }
        int gy = y0 + r, gx = x0 + c;
        flow[(size_t)(b * 2 + f) * NPIX + gy * HW + gx] += s;
    }
}

// ---------------- warp + diff + L2-normalize; x = 1 - diffn channel-last ----------------
__global__ __launch_bounds__(128) void warp_diff_kernel(
    const float* __restrict__ lf0, const float* __restrict__ lf1,
    const float* __restrict__ flow, float* __restrict__ xout)
{
    __shared__ float s_diff[64][129];
    __shared__ float s_ssq[128];
    __shared__ float s_rinv[64];

    const int tid = threadIdx.x;
    const int b = blockIdx.y;
    const int y = blockIdx.x >> 1;
    const int xbase = (blockIdx.x & 1) * 64;
    const int px = tid & 63;
    const int half = tid >> 6;
    const int x = xbase + px;

    float fx = flow[(b * 2 + 0) * NPIX + y * HW + x];
    float fy = flow[(b * 2 + 1) * NPIX + y * HW + x];
    float xs = fminf(fmaxf((float)x + fx, 0.f), 127.f);
    float ys = fminf(fmaxf((float)y + fy, 0.f), 127.f);
    float x0f = floorf(xs), y0f = floorf(ys);
    int ix0 = (int)x0f, iy0 = (int)y0f;
    int ix1 = min(ix0 + 1, 127), iy1 = min(iy0 + 1, 127);
    float wx = xs - x0f, wy = ys - y0f;
    float w00 = (1.f - wx) * (1.f - wy), w01 = wx * (1.f - wy);
    float w10 = (1.f - wx) * wy,         w11 = wx * wy;
    int o00 = iy0 * HW + ix0, o01 = iy0 * HW + ix1;
    int o10 = iy1 * HW + ix0, o11 = iy1 * HW + ix1;

    const float* lf1b = lf1 + (size_t)b * CH * NPIX;
    const float* lf0b = lf0 + (size_t)b * CH * NPIX;
    const int here = y * HW + x;

    float ssq = 0.f;
    for (int c = half * 64; c < half * 64 + 64; ++c) {
        const float* p = lf1b + (size_t)c * NPIX;
        float wv = w00 * p[o00] + w01 * p[o01] + w10 * p[o10] + w11 * p[o11];
        float d = lf0b[(size_t)c * NPIX + here] - wv;
        s_diff[px][c] = d;
        ssq += d * d;
    }
    s_ssq[tid] = ssq;
    __syncthreads();
    if (tid < 64) {
        float s = s_ssq[tid] + s_ssq[tid + 64];
        s_rinv[tid] = 1.f / fmaxf(sqrtf(s), 1e-12f);
    }
    __syncthreads();

    float* xb = xout + ((size_t)b * NPIX + y * HW + xbase) * CH;
    for (int p2 = 0; p2 < 64; ++p2)
        xb[(size_t)p2 * CH + tid] = 1.f - s_diff[p2][tid] * s_rinv[p2];
}

// ---------------- y = M x + bscal = bv.x ----------------
__global__ __launch_bounds__(256) void gemm_y_kernel(
    const float* __restrict__ X, const float* __restrict__ M,
    const float* __restrict__ bv,
    float* __restrict__ Y, float* __restrict__ bscal)
{
    __shared__ float As[8][132];
    __shared__ float Bs[8][132];
    __shared__ float sbv[128];

    const int tid = threadIdx.x;
    const int tx = tid & 15, ty = tid >> 4;
    const int m0 = blockIdx.x * 128;

    if (tid < 128) sbv[tid] = bv[tid];
    __syncthreads();

    float acc[8][8];
    #pragma unroll
    for (int i = 0; i < 8; i++)
        #pragma unroll
        for (int j = 0; j < 8; j++) acc[i][j] = 0.f;

    const int row  = tid >> 1;
    const int part = tid & 1;
    float bdot = 0.f;

    for (int kk = 0; kk < 128; kk += 8) {
        float4 a = *(const float4*)&X[(size_t)(m0 + row) * 128 + kk + part * 4];
        float4 b = *(const float4*)&M[(size_t)row * 128 + kk + part * 4];
        int kb4 = kk + part * 4;
        bdot += a.x * sbv[kb4+0] + a.y * sbv[kb4+1] + a.z * sbv[kb4+2] + a.w * sbv[kb4+3];
        As[part*4+0][row] = a.x; As[part*4+1][row] = a.y;
        As[part*4+2][row] = a.z; As[part*4+3][row] = a.w;
        Bs[part*4+0][row] = b.x; Bs[part*4+1][row] = b.y;
        Bs[part*4+2][row] = b.z; Bs[part*4+3][row] = b.w;
        __syncthreads();
        #pragma unroll
        for (int k = 0; k < 8; k++) {
            float af[8], bf[8];
            *(float4*)&af[0] = *(const float4*)&As[k][ty * 8];
            *(float4*)&af[4] = *(const float4*)&As[k][ty * 8 + 4];
            *(float4*)&bf[0] = *(const float4*)&Bs[k][tx * 8];
            *(float4*)&bf[4] = *(const float4*)&Bs[k][tx * 8 + 4];
            #pragma unroll
            for (int i = 0; i < 8; i++)
                #pragma unroll
                for (int j = 0; j < 8; j++)
                    acc[i][j] += af[i] * bf[j];
        }
        __syncthreads();
    }

    float other = __shfl_xor_sync(0xffffffffu, bdot, 1);
    if (part == 0) bscal[m0 + row] = bdot + other;

    #pragma unroll
    for (int i = 0; i < 8; i++) {
        int m = m0 + ty * 8 + i;
        #pragma unroll
        for (int j = 0; j < 8; j++)
            Y[(size_t)m * 128 + tx * 8 + j] = acc[i][j];
    }
}

// ---------------- smem-tiled 25-tap local attention ----------------
#define AT_SY_PX 132
#define AT_OFF_SX (6*36*AT_SY_PX)
#define AT_OFF_SB (AT_OFF_SX + 2*32*AT_SY_PX)
#define AT_OFF_SF (AT_OFF_SB + 216)
#define AT_SMEM_FLOATS (AT_OFF_SF + 432)
#define AT_SMEM_BYTES (AT_SMEM_FLOATS * 4)

__global__ __launch_bounds__(256) void attn_tiled_kernel(
    const float* __restrict__ X, const float* __restrict__ Y,
    const float* __restrict__ bscal, const float* __restrict__ uvec,
    const float* __restrict__ cconst,
    const float* __restrict__ flow, float* __restrict__ fi)
{
    extern __shared__ float sm[];
    const float SCALE = 0.08838834764831845f;
    const int tid = threadIdx.x;
    const int x0 = blockIdx.x * 32;
    const int y0 = blockIdx.y * 2;
    const int b  = blockIdx.z;
    const int base = b << 14;

    for (int i = tid; i < 6 * 36 * 32; i += 256) {
        int pos = i >> 5, c4 = (i & 31) * 4;
        int r = pos / 36, cc = pos % 36;
        int gy = y0 - 2 + r, gx = x0 - 2 + cc;
        float4 v = make_float4(0.f, 0.f, 0.f, 0.f);
        if ((unsigned)gy < (unsigned)HW && (unsigned)gx < (unsigned)HW)
            v = *(const float4*)&Y[((size_t)(base + gy * HW + gx)) * 128 + c4];
        *(float4*)&sm[(r * 36 + cc) * AT_SY_PX + c4] = v;
    }
    for (int i = tid; i < 2 * 32 * 32; i += 256) {
        int pos = i >> 5, c4 = (i & 31) * 4;
        int py = pos >> 5, px = pos & 31;
        float4 v = *(const float4*)&X[((size_t)(base + (y0 + py) * HW + x0 + px)) * 128 + c4];
        *(float4*)&sm[AT_OFF_SX + (py * 32 + px) * AT_SY_PX + c4] = v;
    }
    for (int i = tid; i < 216; i += 256) {
        int r = i / 36, cc = i % 36;
        int gy = y0 - 2 + r, gx = x0 - 2 + cc;
        bool ok = ((unsigned)gy < (unsigned)HW) && ((unsigned)gx < (unsigned)HW);
        int n = base + gy * HW + gx;
        sm[AT_OFF_SB + i]       = ok ? bscal[n] : 0.f;
        sm[AT_OFF_SF + i]       = ok ? flow[(size_t)(b * 2 + 0) * NPIX + gy * HW + gx] : 0.f;
        sm[AT_OFF_SF + 216 + i] = ok ? flow[(size_t)(b * 2 + 1) * NPIX + gy * HW + gx] : 0.f;
    }
    __syncthreads();

    const int lane = tid & 31;
    const int warp = tid >> 5;
    const int sub  = lane >> 3;
    const int pxl  = warp * 8 + (lane & 7);
    const int ly = pxl >> 5, lx = pxl & 31;
    const int gy = y0 + ly, gx = x0 + lx;

    float4 xr[8];
    {
        const float* xp = &sm[AT_OFF_SX + (ly * 32 + lx) * AT_SY_PX + sub * 32];
        #pragma unroll
        for (int i = 0; i < 8; i++) xr[i] = *(const float4*)&xp[i * 4];
    }

    float ap = 0.f;
    #pragma unroll
    for (int i = 0; i < 8; i++) {
        const float4 u4 = *(const float4*)&uvec[sub * 32 + i * 4];
        ap += xr[i].x * u4.x + xr[i].y * u4.y + xr[i].z * u4.z + xr[i].w * u4.w;
    }
    ap += __shfl_xor_sync(0xffffffffu, ap, 8);
    ap += __shfl_xor_sync(0xffffffffu, ap, 16);
    const float oobs = -(ap + cconst[0]) * SCALE;

    float s[25];
    #pragma unroll
    for (int t = 0; t < 25; t++) {
        const int dy = t / 5 - 2, dx = t % 5 - 2;
        const int ny = gy + dy, nx = gx + dx;
        if ((unsigned)ny < (unsigned)HW && (unsigned)nx < (unsigned)HW) {
            const int r = ly + dy + 2, cc = lx + dx + 2;
            const float* yp = &sm[(r * 36 + cc) * AT_SY_PX + sub * 32];
            float d = 0.f;
            #pragma unroll
            for (int i = 0; i < 8; i++) {
                float4 yv = *(const float4*)&yp[i * 4];
                d += xr[i].x * yv.x + xr[i].y * yv.y + xr[i].z * yv.z + xr[i].w * yv.w;
            }
            d += __shfl_xor_sync(0xffffffffu, d, 8);
            d += __shfl_xor_sync(0xffffffffu, d, 16);
            s[t] = (d + sm[AT_OFF_SB + r * 36 + cc]) * SCALE;
        } else {
            s[t] = oobs;
        }
    }

    float mx = s[0];
    #pragma unroll
    for (int t = 1; t < 25; t++) mx = fmaxf(mx, s[t]);
    float sum = 0.f;
    #pragma unroll
    for (int t = 0; t < 25; t++) { s[t] = expf(s[t] - mx); sum += s[t]; }

    if (sub == 0) {
        float inv = 1.f / sum;
        float c0 = 0.f, c1 = 0.f;
        #pragma unroll
        for (int t = 0; t < 25; t++) {
            const int dy = t / 5 - 2, dx = t % 5 - 2;
            const int ny = gy + dy, nx = gx + dx;
            if ((unsigned)ny < (unsigned)HW && (unsigned)nx < (unsigned)HW) {
                const int r = ly + dy + 2, cc = lx + dx + 2;
                float w = s[t] * inv;
                c0 += w * sm[AT_OFF_SF + r * 36 + cc];
                c1 += w * sm[AT_OFF_SF + 216 + r * 36 + cc];
            }
        }
        fi[(size_t)(b * 2 + 0) * NPIX + gy * HW + gx] = c0;
        fi[(size_t)(b * 2 + 1) * NPIX + gy * HW + gx] = c1;
    }
}

// ---------------- small utility kernels ----------------
__global__ void copy_kernel(float* __restrict__ dst, const float* __restrict__ src, int n) {
    int i = blockIdx.x * 256 + threadIdx.x;
    if (i < n) dst[i] = src[i];
}

// pack hcat = [feat0 | warp(feat1, flow) | flow] NCHW
__global__ __launch_bounds__(128) void pack_kernel(
    const float* __restrict__ feat0, const float* __restrict__ feat1,
    const float* __restrict__ flow, float* __restrict__ hcat)
{
    const int x = threadIdx.x;
    const int y = blockIdx.x;
    const int b = blockIdx.y;
    const int here = y * HW + x;

    float fx = flow[(b * 2 + 0) * NPIX + here];
    float fy = flow[(b * 2 + 1) * NPIX + here];
    float xs = fminf(fmaxf((float)x + fx, 0.f), 127.f);
    float ys = fminf(fmaxf((float)y + fy, 0.f), 127.f);
    float x0f = floorf(xs), y0f = floorf(ys);
    int ix0 = (int)x0f, iy0 = (int)y0f;
    int ix1 = min(ix0 + 1, 127), iy1 = min(iy0 + 1, 127);
    float wx = xs - x0f, wy = ys - y0f;
    float w00 = (1.f - wx) * (1.f - wy), w01 = wx * (1.f - wy);
    float w10 = (1.f - wx) * wy,         w11 = wx * wy;
    int o00 = iy0 * HW + ix0, o01 = iy0 * HW + ix1;
    int o10 = iy1 * HW + ix0, o11 = iy1 * HW + ix1;

    float* hb = hcat + (size_t)b * 258 * NPIX;
    const float* f0 = feat0 + (size_t)b * CH * NPIX;
    const float* f1 = feat1 + (size_t)b * CH * NPIX;

    for (int c = 0; c < CH; c++) {
        hb[(size_t)c * NPIX + here] = f0[(size_t)c * NPIX + here];
        const float* p = f1 + (size_t)c * NPIX;
        hb[(size_t)(CH + c) * NPIX + here] =
            w00 * p[o00] + w01 * p[o01] + w10 * p[o10] + w11 * p[o11];
    }
    hb[(size_t)256 * NPIX + here] = fx;
    hb[(size_t)257 * NPIX + here] = fy;
}

// ---------------- host orchestration ----------------
static float* sym_addr(const void* symbol) {
    void* p = nullptr;
    cudaGetSymbolAddress(&p, symbol);
    return (float*)p;
}

extern "C" void kernel_launch(void* const* d_in, const int* in_sizes, int n_in,
                              void* d_out, int out_size)
{
    (void)in_sizes; (void)n_in; (void)out_size;
    const float* feat0     = (const float*)d_in[0];
    const float* feat1     = (const float*)d_in[1];
    const float* flow_init = (const float*)d_in[2];
    const float* lc_w1 = (const float*)d_in[3];
    const float* lc_b1 = (const float*)d_in[4];
    const float* lc_w2 = (const float*)d_in[5];
    const float* lc_b2 = (const float*)d_in[6];
    const float* qw    = (const float*)d_in[7];
    const float* qb    = (const float*)d_in[8];
    const float* kw    = (const float*)d_in[9];
    const float* kb    = (const float*)d_in[10];
    const float* fr_w1 = (const float*)d_in[11];
    const float* fr_b1 = (const float*)d_in[12];
    const float* fr_w2 = (const float*)d_in[13];
    const float* fr_b2 = (const float*)d_in[14];
    const float* fr_w3 = (const float*)d_in[15];
    const float* fr_b3 = (const float*)d_in[16];
    const float* cf_w1 = (const float*)d_in[17];
    const float* cf_b1 = (const float*)d_in[18];
    const float* cf_w2 = (const float*)d_in[19];
    const float* cf_b2 = (const float*)d_in[20];
    const float* cf_w3 = (const float*)d_in[21];
    const float* cf_b3 = (const float*)d_in[22];

    float* lf0   = sym_addr(g_lf0);
    float* lf1   = sym_addr(g_lf1);
    float* tmp   = sym_addr(g_tmp);
    float* tmp2  = sym_addr(g_tmp2);
    float* xbuf  = sym_addr(g_x);
    float* ybuf  = sym_addr(g_y);
    float* flow  = sym_addr(g_flow);
    float* fi    = sym_addr(g_fi);
    float* hcat  = sym_addr(g_hcat);
    float* h2    = sym_addr(g_h2);
    float* Mbuf  = sym_addr(g_M);
    float* ubuf  = sym_addr(g_u);
    float* bvbuf = sym_addr(g_bv);
    float* cbuf  = sym_addr(g_c);
    float* bscal = sym_addr(g_bscal);
    float* Vbuf  = sym_addr(g_V);
    float* Mwbuf = sym_addr(g_Mw);
    float* U1h   = sym_addr(g_U1h);
    float* U1l   = sym_addr(g_U1l);
    float* U2h   = sym_addr(g_U2h);
    float* U2l   = sym_addr(g_U2l);
    float* Uch   = sym_addr(g_Uch);
    float* Ucl   = sym_addr(g_Ucl);
    float* out_flow = (float*)d_out;
    float* out_conf = (float*)d_out + BATCH * 2 * NPIX;

    cudaFuncSetAttribute(fr_fused_kernel,
                         cudaFuncAttributeMaxDynamicSharedMemorySize, FR_SMEM_BYTES);
    cudaFuncSetAttribute(attn_tiled_kernel,
                         cudaFuncAttributeMaxDynamicSharedMemorySize, AT_SMEM_BYTES);

    // one-time preps
    prepM_kernel<<<128, 128>>>(qw, kw, Mbuf);
    prepUV_kernel<<<1, 128>>>(qw, kw, qb, kb, ubuf, bvbuf, cbuf);
    wino_wt_kernel<<<(128*128 + 255)/256, 256>>>(lc_w1, U1h, U1l, 128, 128, 128);
    wino_wt_kernel<<<(128*128 + 255)/256, 256>>>(lc_w2, U2h, U2l, 128, 128, 128);
    wino_wt_kernel<<<(CFPAD*128 + 255)/256, 256>>>(cf_w1, Uch, Ucl, 258, CFPAD, 128);

    // lc1 (both features, both batches)
    wino_in_kernel<<<dim3(NT_LC/32, 16), 256>>>(feat0, feat1, Vbuf, 128, 128, NT_LC, VPL_LC);
    wino_gemm_tc_kernel<<<dim3(NT_LC/128, 16), 256>>>(U1h, U1l, Vbuf, Mwbuf, 128, NT_LC, 128*128, VPL_LC, MPL_LC);
    wino_out_kernel<<<dim3(NT_LC/32, 16), 256>>>(Mwbuf, lc_b1, tmp, tmp2, 128, NT_LC, MPL_LC, ACT_GELU);
    // lc2
    wino_in_kernel<<<dim3(NT_LC/32, 16), 256>>>(tmp, tmp2, Vbuf, 128, 128, NT_LC, VPL_LC);
    wino_gemm_tc_kernel<<<dim3(NT_LC/128, 16), 256>>>(U2h, U2l, Vbuf, Mwbuf, 128, NT_LC, 128*128, VPL_LC, MPL_LC);
    wino_out_kernel<<<dim3(NT_LC/32, 16), 256>>>(Mwbuf, lc_b2, lf0, lf1, 128, NT_LC, MPL_LC, ACT_NONE);

    copy_kernel<<<(BATCH*2*NPIX + 255)/256, 256>>>(flow, flow_init, BATCH*2*NPIX);

    for (int it = 0; it < ITERS; ++it) {
        warp_diff_kernel<<<dim3(2*HW, BATCH), 128>>>(lf0, lf1, flow, xbuf);
        gemm_y_kernel<<<BATCH*NPIX/128, 256>>>(xbuf, Mbuf, bvbuf, ybuf, bscal);
        attn_tiled_kernel<<<dim3(4, 64, BATCH), 256, AT_SMEM_BYTES>>>(
            xbuf, ybuf, bscal, ubuf, cbuf, flow, fi);
        fr_fused_kernel<<<dim3(8,8,BATCH), 256, FR_SMEM_BYTES>>>(
            fi, fr_w1, fr_b1, fr_w2, fr_b2, fr_w3, fr_b3, flow);
    }

    // confidence head
    pack_kernel<<<dim3(HW, BATCH), 128>>>(feat0, feat1, flow, hcat);
    // cf1 via Winograd (Cin=258 -> pad 272)
    wino_in_kernel<<<dim3(NT_CF/32, CFPAD/8), 256>>>(hcat, hcat, Vbuf, 258, CFPAD, NT_CF, VPL_CF);
    wino_gemm_tc_kernel<<<dim3(NT_CF/128, 16), 256>>>(Uch, Ucl, Vbuf, Mwbuf, CFPAD, NT_CF, CFPAD*128, VPL_CF, MPL_CF);
    wino_out_kernel<<<dim3(NT_CF/32, 16), 256>>>(Mwbuf, cf_b1, tmp, tmp, 128, NT_CF, MPL_CF, ACT_GELU);
    // cf2 / cf3 direct
    conv3x3_kernel<16><<<dim3(4,4,BATCH*4), 256>>>(tmp, cf_w2, cf_b2, h2, 128, 64, ACT_GELU);
    conv3x3_kernel<2><<<dim3(4,4,BATCH), 256>>>(h2, cf_w3, cf_b3, out_conf, 64, 1, ACT_SIGM);

    copy_kernel<<<(BATCH*2*NPIX + 255)/256, 256>>>(out_flow, flow, BATCH*2*NPIX);
}

// round 11
// speedup vs baseline: 1.2983x; 1.2983x over previous
#include <cuda_runtime.h>
#include <stdint.h>
#include <math.h>

#define HW     128
#define BATCH  2
#define CH     128
#define NPIX   (HW*HW)            // 16384
#define ITERS  10

#define NT_LC   16384             // 4 images x 4096 tiles
#define NT_CF   8192              // 2 images
#define CFPAD   264               // cf1 cin pad (multiple of 8)
#define VPL_LC  (128*NT_LC)
#define VPL_CF  (CFPAD*NT_CF)
#define MPL_LC  (128*NT_LC)
#define MPL_CF  (128*NT_CF)

// ---------------- scratch (static device allocations; no cudaMalloc) ----------------
__device__ float g_lf0 [BATCH*CH*NPIX];
__device__ float g_lf1 [BATCH*CH*NPIX];
__device__ float g_tmp [BATCH*CH*NPIX];
__device__ float g_tmp2[BATCH*CH*NPIX];
__device__ float g_x   [BATCH*NPIX*CH];
__device__ float g_y   [BATCH*NPIX*CH];
__device__ float g_flow[BATCH*2*NPIX];
__device__ float g_fi  [BATCH*2*NPIX];
__device__ float g_hcat[BATCH*258*NPIX];
__device__ float g_h2  [BATCH*64*NPIX];
__device__ float g_M   [CH*CH];
__device__ float g_u   [CH];
__device__ float g_bv  [CH];
__device__ float g_c   [1];
__device__ float g_bscal[BATCH*NPIX];
// Winograd buffers
__device__ float g_V  [16 * VPL_CF];
__device__ float g_Mw [16 * MPL_LC];
__device__ float g_U1 [16 * 128 * 128];
__device__ float g_U2 [16 * 128 * 128];
__device__ float g_Uc [16 * CFPAD * 128];

// ---------------- helpers ----------------
__device__ __forceinline__ float gelu_f(float v) {
    return 0.5f * v * (1.0f + erff(v * 0.70710678118654752f));
}
__device__ __forceinline__ float sigmoid_f(float v) {
    return 1.0f / (1.0f + expf(-v));
}
// packed f32x2 helpers (Blackwell FFMA2 — only reachable via PTX)
__device__ __forceinline__ unsigned long long pack2(float a, float b) {
    unsigned long long r;
    asm("mov.b64 %0, {%1, %2};" : "=l"(r) : "f"(a), "f"(b));
    return r;
}
__device__ __forceinline__ void fma2(unsigned long long& acc, unsigned long long a, unsigned long long b) {
    asm("fma.rn.f32x2 %0, %1, %2, %0;" : "+l"(acc) : "l"(a), "l"(b));
}
__device__ __forceinline__ float2 unpack2(unsigned long long v) {
    float2 r;
    asm("mov.b64 {%0, %1}, %2;" : "=f"(r.x), "=f"(r.y) : "l"(v));
    return r;
}

#define ACT_NONE 0
#define ACT_GELU 1
#define ACT_SIGM 2

// ---------------- prep: M = Wq^T Wk ; u = Wq^T kb ; bv = Wk^T qb ; c = qb.kb ----------------
__global__ void prepM_kernel(const float* __restrict__ qw, const float* __restrict__ kw,
                             float* __restrict__ M)
{
    int i = blockIdx.x, j = threadIdx.x;
    float s = 0.f;
    for (int d = 0; d < CH; d++)
        s += qw[d * CH + i] * kw[d * CH + j];
    M[i * CH + j] = s;
}

__global__ void prepUV_kernel(const float* __restrict__ qw, const float* __restrict__ kw,
                              const float* __restrict__ qb, const float* __restrict__ kb,
                              float* __restrict__ u, float* __restrict__ bv, float* __restrict__ c)
{
    int j = threadIdx.x;
    float su = 0.f, sb = 0.f;
    for (int d = 0; d < CH; d++) {
        su += qw[d * CH + j] * kb[d];
        sb += kw[d * CH + j] * qb[d];
    }
    u[j] = su;
    bv[j] = sb;
    if (j == 0) {
        float cc = 0.f;
        for (int d = 0; d < CH; d++) cc += qb[d] * kb[d];
        c[0] = cc;
    }
}

// ---------------- Winograd F(2x2,3x3) ----------------
__global__ void wino_wt_kernel(const float* __restrict__ w, float* __restrict__ U,
                               int Cin, int CinPad, int Cout)
{
    int i = blockIdx.x * 256 + threadIdx.x;
    if (i >= CinPad * Cout) return;
    int ci = i / Cout, co = i % Cout;
    float g[3][3];
    #pragma unroll
    for (int r = 0; r < 3; r++)
        #pragma unroll
        for (int cc = 0; cc < 3; cc++)
            g[r][cc] = (ci < Cin) ? w[((size_t)co * Cin + ci) * 9 + r * 3 + cc] : 0.f;
    float t[4][3];
    #pragma unroll
    for (int cc = 0; cc < 3; cc++) {
        t[0][cc] = g[0][cc];
        t[1][cc] = 0.5f * (g[0][cc] + g[1][cc] + g[2][cc]);
        t[2][cc] = 0.5f * (g[0][cc] - g[1][cc] + g[2][cc]);
        t[3][cc] = g[2][cc];
    }
    float u4[4][4];
    #pragma unroll
    for (int r = 0; r < 4; r++) {
        u4[r][0] = t[r][0];
        u4[r][1] = 0.5f * (t[r][0] + t[r][1] + t[r][2]);
        u4[r][2] = 0.5f * (t[r][0] - t[r][1] + t[r][2]);
        u4[r][3] = t[r][2];
    }
    #pragma unroll
    for (int r = 0; r < 4; r++)
        #pragma unroll
        for (int cc = 0; cc < 4; cc++)
            U[(size_t)(r * 4 + cc) * CinPad * Cout + (size_t)ci * Cout + co] = u4[r][cc];
}

// input transform: V[t][ci][tile]
__global__ __launch_bounds__(256) void wino_in_kernel(
    const float* __restrict__ srcA, const float* __restrict__ srcB,
    float* __restrict__ V, int Cin, int CinPad, int NT, int vplane)
{
    const int tg = blockIdx.x * 32 + (threadIdx.x & 31);
    const int ci = blockIdx.y * 8 + (threadIdx.x >> 5);
    const int img = tg >> 12;
    const int within = tg & 4095;
    const int ty = within >> 6, tx = within & 63;
    const float* src = (img < 2) ? srcA : srcB;
    const int b = img & 1;

    float d[4][4];
    if (ci < Cin) {
        const float* p = src + (size_t)(b * Cin + ci) * NPIX;
        const int yb = 2 * ty - 1, xb = 2 * tx - 1;
        #pragma unroll
        for (int r = 0; r < 4; r++) {
            int yy = yb + r;
            #pragma unroll
            for (int cc = 0; cc < 4; cc++) {
                int xx = xb + cc;
                d[r][cc] = ((unsigned)yy < (unsigned)HW && (unsigned)xx < (unsigned)HW)
                         ? p[yy * HW + xx] : 0.f;
            }
        }
    } else {
        #pragma unroll
        for (int r = 0; r < 4; r++)
            #pragma unroll
            for (int cc = 0; cc < 4; cc++) d[r][cc] = 0.f;
    }

    float tm[4][4];
    #pragma unroll
    for (int j = 0; j < 4; j++) {
        tm[0][j] = d[0][j] - d[2][j];
        tm[1][j] = d[1][j] + d[2][j];
        tm[2][j] = d[2][j] - d[1][j];
        tm[3][j] = d[1][j] - d[3][j];
    }
    float v4[4][4];
    #pragma unroll
    for (int i = 0; i < 4; i++) {
        v4[i][0] = tm[i][0] - tm[i][2];
        v4[i][1] = tm[i][1] + tm[i][2];
        v4[i][2] = tm[i][2] - tm[i][1];
        v4[i][3] = tm[i][1] - tm[i][3];
    }
    #pragma unroll
    for (int r = 0; r < 4; r++)
        #pragma unroll
        for (int cc = 0; cc < 4; cc++)
            V[(size_t)(r * 4 + cc) * vplane + (size_t)ci * NT + tg] = v4[r][cc];
}

// per-t GEMM: Mw[t][co][tile] = sum_ci U[t][ci][co] * V[t][ci][tile]  (packed f32x2 core)
__global__ __launch_bounds__(256) void wino_gemm_kernel(
    const float* __restrict__ U, const float* __restrict__ V, float* __restrict__ Mw,
    int CinPad, int NT, int uplane, int vplane, int mplane)
{
    __shared__ float As[8][132];
    __shared__ float Bs[8][132];

    const int tid = threadIdx.x;
    const int tx = tid & 15, ty = tid >> 4;
    const int t16 = blockIdx.y;
    const int n0 = blockIdx.x * 128;
    const float* Ut = U + (size_t)t16 * uplane;
    const float* Vt = V + (size_t)t16 * vplane;
    float* Mt = Mw + (size_t)t16 * mplane;

    unsigned long long acc2[8][4];
    #pragma unroll
    for (int i = 0; i < 8; i++)
        #pragma unroll
        for (int j = 0; j < 4; j++) acc2[i][j] = 0ull;

    const int krow = tid >> 5;        // 0..7
    const int col4 = (tid & 31) * 4;  // 0..124

    for (int k0 = 0; k0 < CinPad; k0 += 8) {
        float4 a = *(const float4*)&Ut[(size_t)(k0 + krow) * 128 + col4];
        float4 b = *(const float4*)&Vt[(size_t)(k0 + krow) * NT + n0 + col4];
        *(float4*)&As[krow][col4] = a;
        *(float4*)&Bs[krow][col4] = b;
        __syncthreads();
        #pragma unroll
        for (int k = 0; k < 8; k++) {
            float af[8];
            *(float4*)&af[0] = *(const float4*)&As[k][ty * 8];
            *(float4*)&af[4] = *(const float4*)&As[k][ty * 8 + 4];
            unsigned long long bp[4];
            #pragma unroll
            for (int j = 0; j < 4; j++)
                bp[j] = *(const unsigned long long*)&Bs[k][tx * 8 + j * 2];
            #pragma unroll
            for (int i = 0; i < 8; i++) {
                unsigned long long ap = pack2(af[i], af[i]);
                #pragma unroll
                for (int j = 0; j < 4; j++)
                    fma2(acc2[i][j], ap, bp[j]);
            }
        }
        __syncthreads();
    }

    #pragma unroll
    for (int i = 0; i < 8; i++) {
        float out8[8];
        #pragma unroll
        for (int j = 0; j < 4; j++) {
            float2 v = unpack2(acc2[i][j]);
            out8[j * 2] = v.x; out8[j * 2 + 1] = v.y;
        }
        float* row = Mt + (size_t)(ty * 8 + i) * NT + n0 + tx * 8;
        *(float4*)&row[0] = *(float4*)&out8[0];
        *(float4*)&row[4] = *(float4*)&out8[4];
    }
}

// inverse transform + bias + act -> NCHW dst
__global__ __launch_bounds__(256) void wino_out_kernel(
    const float* __restrict__ Mw, const float* __restrict__ bias,
    float* __restrict__ dstA, float* __restrict__ dstB,
    int Cout, int NT, int mplane, int act)
{
    const int tg = blockIdx.x * 32 + (threadIdx.x & 31);
    const int co = blockIdx.y * 8 + (threadIdx.x >> 5);
    const int img = tg >> 12;
    const int within = tg & 4095;
    const int ty = within >> 6, tx = within & 63;
    float* dst = (img < 2) ? dstA : dstB;
    const int b = img & 1;

    float m[4][4];
    #pragma unroll
    for (int r = 0; r < 4; r++)
        #pragma unroll
        for (int cc = 0; cc < 4; cc++)
            m[r][cc] = Mw[(size_t)(r * 4 + cc) * mplane + (size_t)co * NT + tg];

    float s[2][4];
    #pragma unroll
    for (int j = 0; j < 4; j++) {
        s[0][j] = m[0][j] + m[1][j] + m[2][j];
        s[1][j] = m[1][j] - m[2][j] - m[3][j];
    }
    float bvv = bias[co];
    float y00 = s[0][0] + s[0][1] + s[0][2] + bvv;
    float y01 = s[0][1] - s[0][2] - s[0][3] + bvv;
    float y10 = s[1][0] + s[1][1] + s[1][2] + bvv;
    float y11 = s[1][1] - s[1][2] - s[1][3] + bvv;
    if (act == ACT_GELU) {
        y00 = gelu_f(y00); y01 = gelu_f(y01); y10 = gelu_f(y10); y11 = gelu_f(y11);
    }
    float* q = dst + (size_t)(b * Cout + co) * NPIX + (2 * ty) * HW + 2 * tx;
    q[0] = y00; q[1] = y01; q[HW] = y10; q[HW + 1] = y11;
}

// ---------------- direct NCHW 3x3 conv (cf2 / cf3) ----------------
template<int COT>
__global__ __launch_bounds__(256, 2) void conv3x3_kernel(
    const float* __restrict__ in, const float* __restrict__ wgt,
    const float* __restrict__ bias, float* __restrict__ out,
    int Cin, int Cout, int act)
{
    __shared__ float s_in[8][34][34];
    __shared__ __align__(16) float s_w[8][COT][12];

    const int tid = threadIdx.x;
    const int tx = tid & 15, ty = tid >> 4;
    const int x0 = blockIdx.x * 32, y0 = blockIdx.y * 32;
    const int nco = (Cout + COT - 1) / COT;
    const int bb  = blockIdx.z / nco;
    const int co0 = (blockIdx.z % nco) * COT;

    float acc[COT][2][2];
    #pragma unroll
    for (int c = 0; c < COT; c++)
        #pragma unroll
        for (int i = 0; i < 2; i++)
            #pragma unroll
            for (int j = 0; j < 2; j++) acc[c][i][j] = 0.f;

    for (int c0 = 0; c0 < Cin; c0 += 8) {
        for (int idx = tid; idx < 8 * 1156; idx += 256) {
            int ci = idx / 1156;
            int r  = (idx % 1156) / 34;
            int cc = idx % 34;
            int gy = y0 - 1 + r, gx = x0 - 1 + cc;
            int cin = c0 + ci;
            float v = 0.f;
            if (cin < Cin && (unsigned)gy < (unsigned)HW && (unsigned)gx < (unsigned)HW)
                v = in[((size_t)(bb * Cin + cin) * HW + gy) * HW + gx];
            s_in[ci][r][cc] = v;
        }
        for (int idx = tid; idx < 8 * COT * 9; idx += 256) {
            int ci = idx / (COT * 9);
            int co = (idx % (COT * 9)) / 9;
            int k  = idx % 9;
            int cin = c0 + ci, cog = co0 + co;
            float v = 0.f;
            if (cin < Cin && cog < Cout)
                v = wgt[((size_t)cog * Cin + cin) * 9 + k];
            s_w[ci][co][k] = v;
        }
        __syncthreads();

        #pragma unroll
        for (int ci = 0; ci < 8; ci++) {
            float v[4][4];
            #pragma unroll
            for (int i = 0; i < 4; i++) {
                float2 a = *(const float2*)&s_in[ci][ty * 2 + i][tx * 2];
                float2 b = *(const float2*)&s_in[ci][ty * 2 + i][tx * 2 + 2];
                v[i][0] = a.x; v[i][1] = a.y; v[i][2] = b.x; v[i][3] = b.y;
            }
            #pragma unroll
            for (int co = 0; co < COT; co++) {
                float4 wa = *(const float4*)&s_w[ci][co][0];
                float4 wb = *(const float4*)&s_w[ci][co][4];
                float w8  = s_w[ci][co][8];
                #pragma unroll
                for (int i2 = 0; i2 < 2; i2++)
                    #pragma unroll
                    for (int j2 = 0; j2 < 2; j2++) {
                        float a = acc[co][i2][j2];
                        a += v[i2+0][j2+0] * wa.x;
                        a += v[i2+0][j2+1] * wa.y;
                        a += v[i2+0][j2+2] * wa.z;
                        a += v[i2+1][j2+0] * wa.w;
                        a += v[i2+1][j2+1] * wb.x;
                        a += v[i2+1][j2+2] * wb.y;
                        a += v[i2+2][j2+0] * wb.z;
                        a += v[i2+2][j2+1] * wb.w;
                        a += v[i2+2][j2+2] * w8;
                        acc[co][i2][j2] = a;
                    }
            }
        }
        __syncthreads();
    }

    #pragma unroll
    for (int co = 0; co < COT; co++) {
        int cog = co0 + co;
        if (cog >= Cout) break;
        float bvv = bias[cog];
        #pragma unroll
        for (int i2 = 0; i2 < 2; i2++)
            #pragma unroll
            for (int j2 = 0; j2 < 2; j2++) {
                int oy = y0 + ty * 2 + i2, ox = x0 + tx * 2 + j2;
                float v = acc[co][i2][j2] + bvv;
                if (act == ACT_GELU) v = gelu_f(v);
                else if (act == ACT_SIGM) v = sigmoid_f(v);
                out[((size_t)(bb * Cout + cog) * HW + oy) * HW + ox] = v;
            }
    }
}

// ---------------- fused flow-refiner chain ----------------
#define FR_OFF_W1 0
#define FR_OFF_B1 288
#define FR_OFF_W2 304
#define FR_OFF_B2 2608
#define FR_OFF_W3 2624
#define FR_OFF_B3 2912
#define FR_OFF_FI 2916
#define FR_OFF_T1 3884
#define FR_OFF_T2 10284
#define FR_SMEM_FLOATS 15468
#define FR_SMEM_BYTES (FR_SMEM_FLOATS * 4)

__global__ __launch_bounds__(256) void fr_fused_kernel(
    const float* __restrict__ fi,
    const float* __restrict__ w1, const float* __restrict__ b1,
    const float* __restrict__ w2, const float* __restrict__ b2,
    const float* __restrict__ w3, const float* __restrict__ b3,
    float* __restrict__ flow)
{
    extern __shared__ float sm[];
    const int tid = threadIdx.x;
    const int x0 = blockIdx.x * 16, y0 = blockIdx.y * 16;
    const int b = blockIdx.z;

    for (int u = tid; u < 288;  u += 256) sm[FR_OFF_W1 + u] = w1[u];
    for (int u = tid; u < 16;   u += 256) sm[FR_OFF_B1 + u] = b1[u];
    for (int u = tid; u < 2304; u += 256) sm[FR_OFF_W2 + u] = w2[u];
    for (int u = tid; u < 16;   u += 256) sm[FR_OFF_B2 + u] = b2[u];
    for (int u = tid; u < 288;  u += 256) sm[FR_OFF_W3 + u] = w3[u];
    for (int u = tid; u < 2;    u += 256) sm[FR_OFF_B3 + u] = b3[u];
    for (int u = tid; u < 2 * 484; u += 256) {
        int ci = u / 484;
        int rem = u % 484;
        int r = rem / 22, c = rem % 22;
        int gy = y0 - 3 + r, gx = x0 - 3 + c;
        float v = 0.f;
        if ((unsigned)gy < (unsigned)HW && (unsigned)gx < (unsigned)HW)
            v = fi[(size_t)(b * 2 + ci) * NPIX + gy * HW + gx];
        sm[FR_OFF_FI + u] = v;
    }
    __syncthreads();

    for (int u = tid; u < 16 * 400; u += 256) {
        int co = u / 400;
        int rem = u % 400;
        int r = rem / 20, c = rem % 20;
        int gy = y0 - 2 + r, gx = x0 - 2 + c;
        float v = 0.f;
        if ((unsigned)gy < (unsigned)HW && (unsigned)gx < (unsigned)HW) {
            float s = sm[FR_OFF_B1 + co];
            #pragma unroll
            for (int ci = 0; ci < 2; ci++)
                #pragma unroll
                for (int dy = 0; dy < 3; dy++)
                    #pragma unroll
                    for (int dx = 0; dx < 3; dx++)
                        s += sm[FR_OFF_FI + (ci * 22 + r + dy) * 22 + c + dx]
                           * sm[FR_OFF_W1 + (co * 2 + ci) * 9 + dy * 3 + dx];
            v = gelu_f(s);
        }
        sm[FR_OFF_T1 + u] = v;
    }
    __syncthreads();

    for (int u = tid; u < 16 * 324; u += 256) {
        int co = u / 324;
        int rem = u % 324;
        int r = rem / 18, c = rem % 18;
        int gy = y0 - 1 + r, gx = x0 - 1 + c;
        float v = 0.f;
        if ((unsigned)gy < (unsigned)HW && (unsigned)gx < (unsigned)HW) {
            float s = sm[FR_OFF_B2 + co];
            #pragma unroll
            for (int ci = 0; ci < 16; ci++) {
                const float* t1p = &sm[FR_OFF_T1 + (ci * 20 + r) * 20 + c];
                const float* wp  = &sm[FR_OFF_W2 + (co * 16 + ci) * 9];
                s += t1p[0]  * wp[0] + t1p[1]  * wp[1] + t1p[2]  * wp[2];
                s += t1p[20] * wp[3] + t1p[21] * wp[4] + t1p[22] * wp[5];
                s += t1p[40] * wp[6] + t1p[41] * wp[7] + t1p[42] * wp[8];
            }
            v = gelu_f(s);
        }
        sm[FR_OFF_T2 + u] = v;
    }
    __syncthreads();

    for (int u = tid; u < 2 * 256; u += 256) {
        int f = u / 256;
        int rem = u % 256;
        int r = rem / 16, c = rem % 16;
        float s = sm[FR_OFF_B3 + f];
        #pragma unroll
        for (int ci = 0; ci < 16; ci++) {
            const float* t2p = &sm[FR_OFF_T2 + (ci * 18 + r) * 18 + c];
            const float* wp  = &sm[FR_OFF_W3 + (f * 16 + ci) * 9];
            s += t2p[0]  * wp[0] + t2p[1]  * wp[1] + t2p[2]  * wp[2];
            s += t2p[18] * wp[3] + t2p[19] * wp[4] + t2p[20] * wp[5];
            s += t2p[36] * wp[6] + t2p[37] * wp[7] + t2p[38] * wp[8];
        }
        int gy = y0 + r, gx = x0 + c;
        flow[(size_t)(b * 2 + f) * NPIX + gy * HW + gx] += s;
    }
}

// ---------------- warp + diff + L2-normalize; x = 1 - diffn channel-last ----------------
__global__ __launch_bounds__(128) void warp_diff_kernel(
    const float* __restrict__ lf0, const float* __restrict__ lf1,
    const float* __restrict__ flow, float* __restrict__ xout)
{
    __shared__ float s_diff[64][129];
    __shared__ float s_ssq[128];
    __shared__ float s_rinv[64];

    const int tid = threadIdx.x;
    const int b = blockIdx.y;
    const int y = blockIdx.x >> 1;
    const int xbase = (blockIdx.x & 1) * 64;
    const int px = tid & 63;
    const int half = tid >> 6;
    const int x = xbase + px;

    float fx = flow[(b * 2 + 0) * NPIX + y * HW + x];
    float fy = flow[(b * 2 + 1) * NPIX + y * HW + x];
    float xs = fminf(fmaxf((float)x + fx, 0.f), 127.f);
    float ys = fminf(fmaxf((float)y + fy, 0.f), 127.f);
    float x0f = floorf(xs), y0f = floorf(ys);
    int ix0 = (int)x0f, iy0 = (int)y0f;
    int ix1 = min(ix0 + 1, 127), iy1 = min(iy0 + 1, 127);
    float wx = xs - x0f, wy = ys - y0f;
    float w00 = (1.f - wx) * (1.f - wy), w01 = wx * (1.f - wy);
    float w10 = (1.f - wx) * wy,         w11 = wx * wy;
    int o00 = iy0 * HW + ix0, o01 = iy0 * HW + ix1;
    int o10 = iy1 * HW + ix0, o11 = iy1 * HW + ix1;

    const float* lf1b = lf1 + (size_t)b * CH * NPIX;
    const float* lf0b = lf0 + (size_t)b * CH * NPIX;
    const int here = y * HW + x;

    float ssq = 0.f;
    for (int c = half * 64; c < half * 64 + 64; ++c) {
        const float* p = lf1b + (size_t)c * NPIX;
        float wv = w00 * p[o00] + w01 * p[o01] + w10 * p[o10] + w11 * p[o11];
        float d = lf0b[(size_t)c * NPIX + here] - wv;
        s_diff[px][c] = d;
        ssq += d * d;
    }
    s_ssq[tid] = ssq;
    __syncthreads();
    if (tid < 64) {
        float s = s_ssq[tid] + s_ssq[tid + 64];
        s_rinv[tid] = 1.f / fmaxf(sqrtf(s), 1e-12f);
    }
    __syncthreads();

    float* xb = xout + ((size_t)b * NPIX + y * HW + xbase) * CH;
    for (int p2 = 0; p2 < 64; ++p2)
        xb[(size_t)p2 * CH + tid] = 1.f - s_diff[p2][tid] * s_rinv[p2];
}

// ---------------- y = M x + bscal = bv.x  (packed f32x2 core) ----------------
__global__ __launch_bounds__(256) void gemm_y_kernel(
    const float* __restrict__ X, const float* __restrict__ M,
    const float* __restrict__ bv,
    float* __restrict__ Y, float* __restrict__ bscal)
{
    __shared__ float As[8][132];
    __shared__ float Bs[8][132];
    __shared__ float sbv[128];

    const int tid = threadIdx.x;
    const int tx = tid & 15, ty = tid >> 4;
    const int m0 = blockIdx.x * 128;

    if (tid < 128) sbv[tid] = bv[tid];
    __syncthreads();

    unsigned long long acc2[8][4];
    #pragma unroll
    for (int i = 0; i < 8; i++)
        #pragma unroll
        for (int j = 0; j < 4; j++) acc2[i][j] = 0ull;

    const int row  = tid >> 1;
    const int part = tid & 1;
    float bdot = 0.f;

    for (int kk = 0; kk < 128; kk += 8) {
        float4 a = *(const float4*)&X[(size_t)(m0 + row) * 128 + kk + part * 4];
        float4 b = *(const float4*)&M[(size_t)row * 128 + kk + part * 4];
        int kb4 = kk + part * 4;
        bdot += a.x * sbv[kb4+0] + a.y * sbv[kb4+1] + a.z * sbv[kb4+2] + a.w * sbv[kb4+3];
        As[part*4+0][row] = a.x; As[part*4+1][row] = a.y;
        As[part*4+2][row] = a.z; As[part*4+3][row] = a.w;
        Bs[part*4+0][row] = b.x; Bs[part*4+1][row] = b.y;
        Bs[part*4+2][row] = b.z; Bs[part*4+3][row] = b.w;
        __syncthreads();
        #pragma unroll
        for (int k = 0; k < 8; k++) {
            float af[8];
            *(float4*)&af[0] = *(const float4*)&As[k][ty * 8];
            *(float4*)&af[4] = *(const float4*)&As[k][ty * 8 + 4];
            unsigned long long bp[4];
            #pragma unroll
            for (int j = 0; j < 4; j++)
                bp[j] = *(const unsigned long long*)&Bs[k][tx * 8 + j * 2];
            #pragma unroll
            for (int i = 0; i < 8; i++) {
                unsigned long long ap = pack2(af[i], af[i]);
                #pragma unroll
                for (int j = 0; j < 4; j++)
                    fma2(acc2[i][j], ap, bp[j]);
            }
        }
        __syncthreads();
    }

    float other = __shfl_xor_sync(0xffffffffu, bdot, 1);
    if (part == 0) bscal[m0 + row] = bdot + other;

    #pragma unroll
    for (int i = 0; i < 8; i++) {
        int m = m0 + ty * 8 + i;
        float out8[8];
        #pragma unroll
        for (int j = 0; j < 4; j++) {
            float2 v = unpack2(acc2[i][j]);
            out8[j * 2] = v.x; out8[j * 2 + 1] = v.y;
        }
        *(float4*)&Y[(size_t)m * 128 + tx * 8]     = *(float4*)&out8[0];
        *(float4*)&Y[(size_t)m * 128 + tx * 8 + 4] = *(float4*)&out8[4];
    }
}

// ---------------- smem-tiled 25-tap local attention ----------------
#define AT_SY_PX 132
#define AT_OFF_SX (6*36*AT_SY_PX)
#define AT_OFF_SB (AT_OFF_SX + 2*32*AT_SY_PX)
#define AT_OFF_SF (AT_OFF_SB + 216)
#define AT_SMEM_FLOATS (AT_OFF_SF + 432)
#define AT_SMEM_BYTES (AT_SMEM_FLOATS * 4)

__global__ __launch_bounds__(256) void attn_tiled_kernel(
    const float* __restrict__ X, const float* __restrict__ Y,
    const float* __restrict__ bscal, const float* __restrict__ uvec,
    const float* __restrict__ cconst,
    const float* __restrict__ flow, float* __restrict__ fi)
{
    extern __shared__ float sm[];
    const float SCALE = 0.08838834764831845f;
    const int tid = threadIdx.x;
    const int x0 = blockIdx.x * 32;
    const int y0 = blockIdx.y * 2;
    const int b  = blockIdx.z;
    const int base = b << 14;

    for (int i = tid; i < 6 * 36 * 32; i += 256) {
        int pos = i >> 5, c4 = (i & 31) * 4;
        int r = pos / 36, cc = pos % 36;
        int gy = y0 - 2 + r, gx = x0 - 2 + cc;
        float4 v = make_float4(0.f, 0.f, 0.f, 0.f);
        if ((unsigned)gy < (unsigned)HW && (unsigned)gx < (unsigned)HW)
            v = *(const float4*)&Y[((size_t)(base + gy * HW + gx)) * 128 + c4];
        *(float4*)&sm[(r * 36 + cc) * AT_SY_PX + c4] = v;
    }
    for (int i = tid; i < 2 * 32 * 32; i += 256) {
        int pos = i >> 5, c4 = (i & 31) * 4;
        int py = pos >> 5, px = pos & 31;
        float4 v = *(const float4*)&X[((size_t)(base + (y0 + py) * HW + x0 + px)) * 128 + c4];
        *(float4*)&sm[AT_OFF_SX + (py * 32 + px) * AT_SY_PX + c4] = v;
    }
    for (int i = tid; i < 216; i += 256) {
        int r = i / 36, cc = i % 36;
        int gy = y0 - 2 + r, gx = x0 - 2 + cc;
        bool ok = ((unsigned)gy < (unsigned)HW) && ((unsigned)gx < (unsigned)HW);
        int n = base + gy * HW + gx;
        sm[AT_OFF_SB + i]       = ok ? bscal[n] : 0.f;
        sm[AT_OFF_SF + i]       = ok ? flow[(size_t)(b * 2 + 0) * NPIX + gy * HW + gx] : 0.f;
        sm[AT_OFF_SF + 216 + i] = ok ? flow[(size_t)(b * 2 + 1) * NPIX + gy * HW + gx] : 0.f;
    }
    __syncthreads();

    const int lane = tid & 31;
    const int warp = tid >> 5;
    const int sub  = lane >> 3;
    const int pxl  = warp * 8 + (lane & 7);
    const int ly = pxl >> 5, lx = pxl & 31;
    const int gy = y0 + ly, gx = x0 + lx;

    float4 xr[8];
    {
        const float* xp = &sm[AT_OFF_SX + (ly * 32 + lx) * AT_SY_PX + sub * 32];
        #pragma unroll
        for (int i = 0; i < 8; i++) xr[i] = *(const float4*)&xp[i * 4];
    }

    float ap = 0.f;
    #pragma unroll
    for (int i = 0; i < 8; i++) {
        const float4 u4 = *(const float4*)&uvec[sub * 32 + i * 4];
        ap += xr[i].x * u4.x + xr[i].y * u4.y + xr[i].z * u4.z + xr[i].w * u4.w;
    }
    ap += __shfl_xor_sync(0xffffffffu, ap, 8);
    ap += __shfl_xor_sync(0xffffffffu, ap, 16);
    const float oobs = -(ap + cconst[0]) * SCALE;

    float s[25];
    #pragma unroll
    for (int t = 0; t < 25; t++) {
        const int dy = t / 5 - 2, dx = t % 5 - 2;
        const int ny = gy + dy, nx = gx + dx;
        if ((unsigned)ny < (unsigned)HW && (unsigned)nx < (unsigned)HW) {
            const int r = ly + dy + 2, cc = lx + dx + 2;
            const float* yp = &sm[(r * 36 + cc) * AT_SY_PX + sub * 32];
            float d = 0.f;
            #pragma unroll
            for (int i = 0; i < 8; i++) {
                float4 yv = *(const float4*)&yp[i * 4];
                d += xr[i].x * yv.x + xr[i].y * yv.y + xr[i].z * yv.z + xr[i].w * yv.w;
            }
            d += __shfl_xor_sync(0xffffffffu, d, 8);
            d += __shfl_xor_sync(0xffffffffu, d, 16);
            s[t] = (d + sm[AT_OFF_SB + r * 36 + cc]) * SCALE;
        } else {
            s[t] = oobs;
        }
    }

    float mx = s[0];
    #pragma unroll
    for (int t = 1; t < 25; t++) mx = fmaxf(mx, s[t]);
    float sum = 0.f;
    #pragma unroll
    for (int t = 0; t < 25; t++) { s[t] = expf(s[t] - mx); sum += s[t]; }

    if (sub == 0) {
        float inv = 1.f / sum;
        float c0 = 0.f, c1 = 0.f;
        #pragma unroll
        for (int t = 0; t < 25; t++) {
            const int dy = t / 5 - 2, dx = t % 5 - 2;
            const int ny = gy + dy, nx = gx + dx;
            if ((unsigned)ny < (unsigned)HW && (unsigned)nx < (unsigned)HW) {
                const int r = ly + dy + 2, cc = lx + dx + 2;
                float w = s[t] * inv;
                c0 += w * sm[AT_OFF_SF + r * 36 + cc];
                c1 += w * sm[AT_OFF_SF + 216 + r * 36 + cc];
            }
        }
        fi[(size_t)(b * 2 + 0) * NPIX + gy * HW + gx] = c0;
        fi[(size_t)(b * 2 + 1) * NPIX + gy * HW + gx] = c1;
    }
}

// ---------------- small utility kernels ----------------
__global__ void copy_kernel(float* __restrict__ dst, const float* __restrict__ src, int n) {
    int i = blockIdx.x * 256 + threadIdx.x;
    if (i < n) dst[i] = src[i];
}

// pack hcat = [feat0 | warp(feat1, flow) | flow] NCHW
__global__ __launch_bounds__(128) void pack_kernel(
    const float* __restrict__ feat0, const float* __restrict__ feat1,
    const float* __restrict__ flow, float* __restrict__ hcat)
{
    const int x = threadIdx.x;
    const int y = blockIdx.x;
    const int b = blockIdx.y;
    const int here = y * HW + x;

    float fx = flow[(b * 2 + 0) * NPIX + here];
    float fy = flow[(b * 2 + 1) * NPIX + here];
    float xs = fminf(fmaxf((float)x + fx, 0.f), 127.f);
    float ys = fminf(fmaxf((float)y + fy, 0.f), 127.f);
    float x0f = floorf(xs), y0f = floorf(ys);
    int ix0 = (int)x0f, iy0 = (int)y0f;
    int ix1 = min(ix0 + 1, 127), iy1 = min(iy0 + 1, 127);
    float wx = xs - x0f, wy = ys - y0f;
    float w00 = (1.f - wx) * (1.f - wy), w01 = wx * (1.f - wy);
    float w10 = (1.f - wx) * wy,         w11 = wx * wy;
    int o00 = iy0 * HW + ix0, o01 = iy0 * HW + ix1;
    int o10 = iy1 * HW + ix0, o11 = iy1 * HW + ix1;

    float* hb = hcat + (size_t)b * 258 * NPIX;
    const float* f0 = feat0 + (size_t)b * CH * NPIX;
    const float* f1 = feat1 + (size_t)b * CH * NPIX;

    for (int c = 0; c < CH; c++) {
        hb[(size_t)c * NPIX + here] = f0[(size_t)c * NPIX + here];
        const float* p = f1 + (size_t)c * NPIX;
        hb[(size_t)(CH + c) * NPIX + here] =
            w00 * p[o00] + w01 * p[o01] + w10 * p[o10] + w11 * p[o11];
    }
    hb[(size_t)256 * NPIX + here] = fx;
    hb[(size_t)257 * NPIX + here] = fy;
}

// ---------------- host orchestration ----------------
static float* sym_addr(const void* symbol) {
    void* p = nullptr;
    cudaGetSymbolAddress(&p, symbol);
    return (float*)p;
}

extern "C" void kernel_launch(void* const* d_in, const int* in_sizes, int n_in,
                              void* d_out, int out_size)
{
    (void)in_sizes; (void)n_in; (void)out_size;
    const float* feat0     = (const float*)d_in[0];
    const float* feat1     = (const float*)d_in[1];
    const float* flow_init = (const float*)d_in[2];
    const float* lc_w1 = (const float*)d_in[3];
    const float* lc_b1 = (const float*)d_in[4];
    const float* lc_w2 = (const float*)d_in[5];
    const float* lc_b2 = (const float*)d_in[6];
    const float* qw    = (const float*)d_in[7];
    const float* qb    = (const float*)d_in[8];
    const float* kw    = (const float*)d_in[9];
    const float* kb    = (const float*)d_in[10];
    const float* fr_w1 = (const float*)d_in[11];
    const float* fr_b1 = (const float*)d_in[12];
    const float* fr_w2 = (const float*)d_in[13];
    const float* fr_b2 = (const float*)d_in[14];
    const float* fr_w3 = (const float*)d_in[15];
    const float* fr_b3 = (const float*)d_in[16];
    const float* cf_w1 = (const float*)d_in[17];
    const float* cf_b1 = (const float*)d_in[18];
    const float* cf_w2 = (const float*)d_in[19];
    const float* cf_b2 = (const float*)d_in[20];
    const float* cf_w3 = (const float*)d_in[21];
    const float* cf_b3 = (const float*)d_in[22];

    float* lf0   = sym_addr(g_lf0);
    float* lf1   = sym_addr(g_lf1);
    float* tmp   = sym_addr(g_tmp);
    float* tmp2  = sym_addr(g_tmp2);
    float* xbuf  = sym_addr(g_x);
    float* ybuf  = sym_addr(g_y);
    float* flow  = sym_addr(g_flow);
    float* fi    = sym_addr(g_fi);
    float* hcat  = sym_addr(g_hcat);
    float* h2    = sym_addr(g_h2);
    float* Mbuf  = sym_addr(g_M);
    float* ubuf  = sym_addr(g_u);
    float* bvbuf = sym_addr(g_bv);
    float* cbuf  = sym_addr(g_c);
    float* bscal = sym_addr(g_bscal);
    float* Vbuf  = sym_addr(g_V);
    float* Mwbuf = sym_addr(g_Mw);
    float* U1    = sym_addr(g_U1);
    float* U2    = sym_addr(g_U2);
    float* Uc    = sym_addr(g_Uc);
    float* out_flow = (float*)d_out;
    float* out_conf = (float*)d_out + BATCH * 2 * NPIX;

    cudaFuncSetAttribute(fr_fused_kernel,
                         cudaFuncAttributeMaxDynamicSharedMemorySize, FR_SMEM_BYTES);
    cudaFuncSetAttribute(attn_tiled_kernel,
                         cudaFuncAttributeMaxDynamicSharedMemorySize, AT_SMEM_BYTES);

    // one-time preps
    prepM_kernel<<<128, 128>>>(qw, kw, Mbuf);
    prepUV_kernel<<<1, 128>>>(qw, kw, qb, kb, ubuf, bvbuf, cbuf);
    wino_wt_kernel<<<(128*128 + 255)/256, 256>>>(lc_w1, U1, 128, 128, 128);
    wino_wt_kernel<<<(128*128 + 255)/256, 256>>>(lc_w2, U2, 128, 128, 128);
    wino_wt_kernel<<<(CFPAD*128 + 255)/256, 256>>>(cf_w1, Uc, 258, CFPAD, 128);

    // lc1 (both features, both batches)
    wino_in_kernel<<<dim3(NT_LC/32, 16), 256>>>(feat0, feat1, Vbuf, 128, 128, NT_LC, VPL_LC);
    wino_gemm_kernel<<<dim3(NT_LC/128, 16), 256>>>(U1, Vbuf, Mwbuf, 128, NT_LC, 128*128, VPL_LC, MPL_LC);
    wino_out_kernel<<<dim3(NT_LC/32, 16), 256>>>(Mwbuf, lc_b1, tmp, tmp2, 128, NT_LC, MPL_LC, ACT_GELU);
    // lc2
    wino_in_kernel<<<dim3(NT_LC/32, 16), 256>>>(tmp, tmp2, Vbuf, 128, 128, NT_LC, VPL_LC);
    wino_gemm_kernel<<<dim3(NT_LC/128, 16), 256>>>(U2, Vbuf, Mwbuf, 128, NT_LC, 128*128, VPL_LC, MPL_LC);
    wino_out_kernel<<<dim3(NT_LC/32, 16), 256>>>(Mwbuf, lc_b2, lf0, lf1, 128, NT_LC, MPL_LC, ACT_NONE);

    copy_kernel<<<(BATCH*2*NPIX + 255)/256, 256>>>(flow, flow_init, BATCH*2*NPIX);

    for (int it = 0; it < ITERS; ++it) {
        warp_diff_kernel<<<dim3(2*HW, BATCH), 128>>>(lf0, lf1, flow, xbuf);
        gemm_y_kernel<<<BATCH*NPIX/128, 256>>>(xbuf, Mbuf, bvbuf, ybuf, bscal);
        attn_tiled_kernel<<<dim3(4, 64, BATCH), 256, AT_SMEM_BYTES>>>(
            xbuf, ybuf, bscal, ubuf, cbuf, flow, fi);
        fr_fused_kernel<<<dim3(8,8,BATCH), 256, FR_SMEM_BYTES>>>(
            fi, fr_w1, fr_b1, fr_w2, fr_b2, fr_w3, fr_b3, flow);
    }

    // confidence head
    pack_kernel<<<dim3(HW, BATCH), 128>>>(feat0, feat1, flow, hcat);
    // cf1 via Winograd (Cin=258 -> pad 264)
    wino_in_kernel<<<dim3(NT_CF/32, CFPAD/8), 256>>>(hcat, hcat, Vbuf, 258, CFPAD, NT_CF, VPL_CF);
    wino_gemm_kernel<<<dim3(NT_CF/128, 16), 256>>>(Uc, Vbuf, Mwbuf, CFPAD, NT_CF, CFPAD*128, VPL_CF, MPL_CF);
    wino_out_kernel<<<dim3(NT_CF/32, 16), 256>>>(Mwbuf, cf_b1, tmp, tmp, 128, NT_CF, MPL_CF, ACT_GELU);
    // cf2 / cf3 direct
    conv3x3_kernel<16><<<dim3(4,4,BATCH*4), 256>>>(tmp, cf_w2, cf_b2, h2, 128, 64, ACT_GELU);
    conv3x3_kernel<2><<<dim3(4,4,BATCH), 256>>>(h2, cf_w3, cf_b3, out_conf, 64, 1, ACT_SIGM);

    copy_kernel<<<(BATCH*2*NPIX + 255)/256, 256>>>(out_flow, flow, BATCH*2*NPIX);
}